// round 6
// baseline (speedup 1.0000x reference)
#include <cuda_runtime.h>
#include <math.h>
#include <stdint.h>

#define HH 1024
#define LL 128
#define VOCAB 50257
#define RSTAGE 48                  // rows of out_W staged per block via cp.async.bulk
#define KMAX 12                    // max strided DRAM rows per warp

// ---------------- device scratch (no allocations allowed) ----------------
__device__ float g_scores[LL];
__device__ float g_attn[HH];
__device__ float g_gru_in[HH];
__device__ float g_gh[3 * HH];     // W_hh @ h + b_hh   (r, z, n blocks)
__device__ float g_gi[3 * HH];     // W_ih @ gru_in + b_ih
__device__ float g_bmax[256], g_bsum[256];
__device__ float g_lse;
__device__ unsigned g_flags[256];
__device__ unsigned g_rel[16];

__device__ __forceinline__ float warp_sum(float v) {
#pragma unroll
    for (int o = 16; o > 0; o >>= 1) v += __shfl_down_sync(0xffffffffu, v, o);
    return v;
}

__device__ __forceinline__ void grid_bar(int nb, int bid, int t, int lane,
                                         int wid, unsigned gen) {
    __syncthreads();
    if (t == 0) {
        __threadfence();
        ((volatile unsigned*)g_flags)[bid] = gen;
    }
    if (bid == 0 && wid == 0) {
        bool ok;
        do {
            ok = true;
            for (int i = lane; i < nb; i += 32)
                if (((volatile unsigned*)g_flags)[i] < gen) ok = false;
            ok = __all_sync(0xffffffffu, ok);
        } while (!ok);
        if (lane == 0) {
            __threadfence();
            ((volatile unsigned*)g_rel)[gen] = 1u;
        }
    }
    if (t == 0) {
        while (((volatile unsigned*)g_rel)[gen] == 0u) {}
        __threadfence();
    }
    __syncthreads();
}

__device__ __forceinline__ void lse_combine(float& M, float& S, float m2, float s2) {
    if (m2 > M) { S = S * expf(M - m2) + s2; M = m2; }
    else        { S += s2 * expf(m2 - M); }
}

__device__ __forceinline__ uint32_t smem_u32(const void* p) {
    uint32_t a;
    asm("{ .reg .u64 tmp; cvta.to.shared.u64 tmp, %1; cvt.u32.u64 %0, tmp; }"
        : "=r"(a) : "l"(p));
    return a;
}

extern __shared__ float s_stage[];   // RSTAGE * HH floats (192 KB)

__global__ void __launch_bounds__(1024, 1)
fused_decoder(const int* __restrict__ ids,
              const float* __restrict__ hidden,
              const float* __restrict__ enc,
              const float* __restrict__ emb,
              const float* __restrict__ attn_W,
              const float* __restrict__ attn_b,
              const float* __restrict__ comb_W,
              const float* __restrict__ comb_b,
              const float* __restrict__ W_ih,
              const float* __restrict__ W_hh,
              const float* __restrict__ b_ih,
              const float* __restrict__ b_hh,
              const float* __restrict__ out_W,
              const float* __restrict__ out_b,
              float* __restrict__ out) {
    const int nb = gridDim.x;
    const int t = threadIdx.x, wid = t >> 5, lane = t & 31, bid = blockIdx.x;
    const int task = wid * nb + bid;        // warp-major task id for serial phases
    const int gw   = bid * 32 + wid;        // block-major warp id for logits
    const int totW = nb * 32;
    const int NSTAGED = nb * RSTAGE;
    const int NREM = VOCAB - NSTAGED;

    __shared__ float s_red[1024];
    __shared__ float s_h[HH];
    __shared__ float s_w[LL];
    __shared__ float s_m[2];
    __shared__ float s_bm[32], s_bs[32];
    __shared__ float s_stlog[RSTAGE];
    __shared__ float s_wlog[32 * KMAX];
    __shared__ __align__(8) uint64_t s_mbar;

    const size_t qb = (size_t)ids[0] * HH;
    const float4* q4 = (const float4*)(emb + qb);
    const float4* h4 = (const float4*)hidden;

    // ------- Prologue: kick off async bulk staging of out_W rows into SMEM ---
    if (t == 0) {
        const uint32_t mbar = smem_u32(&s_mbar);
        asm volatile("mbarrier.init.shared.b64 [%0], %1;" :: "r"(mbar), "r"(1) : "memory");
        asm volatile("fence.proxy.async.shared::cta;" ::: "memory");
        const uint32_t total = RSTAGE * HH * 4;
        asm volatile("mbarrier.arrive.expect_tx.shared.b64 _, [%0], %1;"
                     :: "r"(mbar), "r"(total) : "memory");
        const char* src = (const char*)(out_W + (size_t)bid * RSTAGE * HH);
        const uint32_t dst = smem_u32(s_stage);
        const uint32_t CH = 32768;
#pragma unroll
        for (uint32_t c = 0; c < total; c += CH)
            asm volatile("cp.async.bulk.shared::cluster.global.mbarrier::complete_tx::bytes"
                         " [%0], [%1], %2, [%3];"
                         :: "r"(dst + c), "l"(src + c), "r"(CH), "r"(mbar) : "memory");
    }

    // ---------------- Phase 0: gh rows (3072 tasks) + attn scores (128) ------
    if (task < 3 * HH) {
        const int j = task;
        const float4* wr = (const float4*)(W_hh + (size_t)j * HH);
        float acc = 0.f;
#pragma unroll
        for (int i = 0; i < 8; i++) {
            const int idx = lane + 32 * i;
            const float4 v = wr[idx], hv = h4[idx];
            acc += v.x*hv.x + v.y*hv.y + v.z*hv.z + v.w*hv.w;
        }
        acc = warp_sum(acc);
        if (lane == 0) g_gh[j] = acc + b_hh[j];
    } else if (task < 3 * HH + LL) {
        const int l = task - 3 * HH;
        const float4* w = (const float4*)(attn_W + (size_t)l * 2 * HH);
        float acc = 0.f;
#pragma unroll
        for (int i = 0; i < 8; i++) {
            const int idx = lane + 32 * i;
            float4 a = w[idx],       b = q4[idx];
            acc += a.x*b.x + a.y*b.y + a.z*b.z + a.w*b.w;
            float4 c = w[idx + 256], d = h4[idx];
            acc += c.x*d.x + c.y*d.y + c.z*d.z + c.w*d.w;
        }
        acc = warp_sum(acc);
        if (lane == 0) g_scores[l] = acc + attn_b[l];
    }
    grid_bar(nb, bid, t, lane, wid, 1u);

    // ---------------- Phase 1: softmax + attn_applied (blocks 0..7) ----------
    if (bid < 8) {
        float sc = (t < LL) ? g_scores[t] : -INFINITY;
        if (t < LL) {
            float v = sc;
#pragma unroll
            for (int o = 16; o > 0; o >>= 1) v = fmaxf(v, __shfl_down_sync(0xffffffffu, v, o));
            if (lane == 0) s_bm[wid] = v;
        }
        __syncthreads();
        if (t == 0) s_m[0] = fmaxf(fmaxf(s_bm[0], s_bm[1]), fmaxf(s_bm[2], s_bm[3]));
        __syncthreads();
        float e = 0.f;
        if (t < LL) {
            e = expf(sc - s_m[0]);
            float v = warp_sum(e);
            if (lane == 0) s_bs[wid] = v;
        }
        __syncthreads();
        if (t == 0) s_m[1] = 1.f / (s_bs[0] + s_bs[1] + s_bs[2] + s_bs[3]);
        __syncthreads();
        if (t < LL) {
            s_w[t] = e * s_m[1];
            if (bid == 0) out[VOCAB + HH + t] = s_w[t];
        }
        __syncthreads();
        const int col = t & 127, lg = t >> 7;
        const int colg = bid * 128 + col;
        float acc = 0.f;
#pragma unroll
        for (int k = 0; k < 16; k++) {
            const int l = lg * 16 + k;
            acc += s_w[l] * enc[(size_t)l * HH + colg];
        }
        s_red[t] = acc;
        __syncthreads();
        if (t < 128) {
            float a = 0.f;
#pragma unroll
            for (int k = 0; k < 8; k++) a += s_red[t + 128 * k];
            g_attn[colg] = a;
        }
    }
    grid_bar(nb, bid, t, lane, wid, 2u);

    // ---------------- Phase 2: gru_in = relu([q; attn] @ comb_W.T + b) -------
    if (task < HH) {
        const int j = task;
        const float4* wr = (const float4*)(comb_W + (size_t)j * 2 * HH);
        const float4* a4 = (const float4*)g_attn;
        float acc = 0.f;
#pragma unroll
        for (int i = 0; i < 8; i++) {
            const int idx = lane + 32 * i;
            float4 a = wr[idx],       b = q4[idx];
            acc += a.x*b.x + a.y*b.y + a.z*b.z + a.w*b.w;
            float4 c = wr[idx + 256], d = a4[idx];
            acc += c.x*d.x + c.y*d.y + c.z*d.z + c.w*d.w;
        }
        acc = warp_sum(acc);
        if (lane == 0) g_gru_in[j] = fmaxf(acc + comb_b[j], 0.f);
    }
    grid_bar(nb, bid, t, lane, wid, 3u);

    // ---------------- Phase 3: gi rows (3072 independent tasks) --------------
    if (task < 3 * HH) {
        const int j = task;
        const float4* wr = (const float4*)(W_ih + (size_t)j * HH);
        const float4* g4 = (const float4*)g_gru_in;
        float acc = 0.f;
#pragma unroll
        for (int i = 0; i < 8; i++) {
            const int idx = lane + 32 * i;
            const float4 v = wr[idx], gv = g4[idx];
            acc += v.x*gv.x + v.y*gv.y + v.z*gv.z + v.w*gv.w;
        }
        acc = warp_sum(acc);
        if (lane == 0) g_gi[j] = acc + b_ih[j];
    }
    grid_bar(nb, bid, t, lane, wid, 4u);

    // ------- Phase 4 (per-block, barrier-free): gate math -> s_h = h_new -----
    {
        const int j = t;   // 1024 threads, one element each
        const float ir  = g_gi[j];
        const float iz  = g_gi[j + HH];
        const float inn = g_gi[j + 2 * HH];
        const float hr  = g_gh[j];
        const float hz  = g_gh[j + HH];
        const float hn  = g_gh[j + 2 * HH];
        const float hv  = hidden[j];
        const float r = 1.f / (1.f + expf(-(ir + hr)));
        const float z = 1.f / (1.f + expf(-(iz + hz)));
        const float n = tanhf(inn + r * hn);
        const float hnew = (1.f - z) * n + z * hv;
        s_h[j] = hnew;
        if (bid == 0) out[VOCAB + j] = hnew;
        if (t < 32 * KMAX) s_wlog[t] = -INFINITY;
    }
    __syncthreads();

    // ---------------- Phase 5: logits GEMV (DRAM strided + SMEM staged) ------
    {
        const float4* h4s = (const float4*)s_h;
        float m = -INFINITY, s = 0.f;

        // DRAM-streamed rows, 2 rows/warp/iter
        int r = gw, k = 0;
        for (; r + totW < NREM; r += 2 * totW, k += 2) {
            const float4* w0 = (const float4*)(out_W + (size_t)(NSTAGED + r) * HH);
            const float4* w1 = (const float4*)(out_W + (size_t)(NSTAGED + r + totW) * HH);
            float a0 = 0.f, a1 = 0.f;
#pragma unroll
            for (int i = 0; i < 8; i++) {
                const int idx = lane + 32 * i;
                const float4 b = h4s[idx];
                const float4 x = w0[idx];
                const float4 y = w1[idx];
                a0 += x.x*b.x + x.y*b.y + x.z*b.z + x.w*b.w;
                a1 += y.x*b.x + y.y*b.y + y.z*b.z + y.w*b.w;
            }
            a0 = warp_sum(a0); a1 = warp_sum(a1);
            if (lane == 0) {
                const float l0 = a0 + out_b[NSTAGED + r];
                const float l1 = a1 + out_b[NSTAGED + r + totW];
                s_wlog[wid * KMAX + k] = l0;
                s_wlog[wid * KMAX + k + 1] = l1;
                lse_combine(m, s, l0, 1.f);
                lse_combine(m, s, l1, 1.f);
            }
        }
        for (; r < NREM; r += totW, k++) {
            const float4* w0 = (const float4*)(out_W + (size_t)(NSTAGED + r) * HH);
            float a0 = 0.f;
#pragma unroll
            for (int i = 0; i < 8; i++) {
                const int idx = lane + 32 * i;
                const float4 b = h4s[idx];
                const float4 x = w0[idx];
                a0 += x.x*b.x + x.y*b.y + x.z*b.z + x.w*b.w;
            }
            a0 = warp_sum(a0);
            if (lane == 0) {
                const float l0 = a0 + out_b[NSTAGED + r];
                s_wlog[wid * KMAX + k] = l0;
                lse_combine(m, s, l0, 1.f);
            }
        }

        // Wait for staged rows (bulk copy finished long ago) and compute them
        {
            const uint32_t mbar = smem_u32(&s_mbar);
            uint32_t done;
            do {
                asm volatile("{ .reg .pred p;\n\t"
                             "mbarrier.try_wait.parity.shared.b64 p, [%1], 0;\n\t"
                             "selp.b32 %0, 1, 0, p; }"
                             : "=r"(done) : "r"(mbar) : "memory");
            } while (!done);
        }
        for (int j = wid; j < RSTAGE; j += 32) {
            const float4* sr = (const float4*)(s_stage + j * HH);
            float acc = 0.f;
#pragma unroll
            for (int i = 0; i < 8; i++) {
                const int idx = lane + 32 * i;
                const float4 a = sr[idx], b = h4s[idx];
                acc += a.x*b.x + a.y*b.y + a.z*b.z + a.w*b.w;
            }
            acc = warp_sum(acc);
            if (lane == 0) {
                const float l0 = acc + out_b[bid * RSTAGE + j];
                s_stlog[j] = l0;
                lse_combine(m, s, l0, 1.f);
            }
        }
        if (lane == 0) { s_bm[wid] = m; s_bs[wid] = s; }
        __syncthreads();
        if (wid == 0) {
            float M = s_bm[lane], S = s_bs[lane];
#pragma unroll
            for (int o = 16; o > 0; o >>= 1) {
                float m2 = __shfl_down_sync(0xffffffffu, M, o);
                float s2 = __shfl_down_sync(0xffffffffu, S, o);
                lse_combine(M, S, m2, s2);
            }
            if (lane == 0) { g_bmax[bid] = M; g_bsum[bid] = S; }
        }
    }
    grid_bar(nb, bid, t, lane, wid, 5u);

    // ---------------- Phase 6: global LSE ------------------------------------
    if (bid == 0 && wid == 0) {
        float M = -INFINITY, S = 0.f;
        for (int i = lane; i < nb; i += 32) lse_combine(M, S, g_bmax[i], g_bsum[i]);
#pragma unroll
        for (int o = 16; o > 0; o >>= 1) {
            float m2 = __shfl_down_sync(0xffffffffu, M, o);
            float s2 = __shfl_down_sync(0xffffffffu, S, o);
            lse_combine(M, S, m2, s2);
        }
        if (lane == 0) g_lse = M + logf(S);
    }
    grid_bar(nb, bid, t, lane, wid, 6u);

    // ---------------- Phase 7: write log_probs from SMEM ---------------------
    {
        const float lse = g_lse;
        if (t < RSTAGE) out[bid * RSTAGE + t] = s_stlog[t] - lse;
        for (int i = t; i < 32 * KMAX; i += 1024) {
            const int w = i / KMAX, k = i % KMAX;
            const int r = (bid * 32 + w) + k * totW;
            if (r < NREM && s_wlog[i] > -INFINITY)
                out[NSTAGED + r] = s_wlog[i] - lse;
        }
    }

    // ---------------- Epilogue: reset barrier state for next graph replay ----
    __syncthreads();
    if (t == 0) {
        __threadfence();
        ((volatile unsigned*)g_flags)[bid] = 7u;
    }
    if (bid == 0 && wid == 0) {
        bool ok;
        do {
            ok = true;
            for (int i = lane; i < nb; i += 32)
                if (((volatile unsigned*)g_flags)[i] < 7u) ok = false;
            ok = __all_sync(0xffffffffu, ok);
        } while (!ok);
        for (int i = lane; i < nb; i += 32) ((volatile unsigned*)g_flags)[i] = 0u;
        if (lane < 16) ((volatile unsigned*)g_rel)[lane] = 0u;
    }
}

extern "C" void kernel_launch(void* const* d_in, const int* in_sizes, int n_in,
                              void* d_out, int out_size) {
    const int*   ids    = (const int*)  d_in[0];
    const float* hidden = (const float*)d_in[1];
    const float* enc    = (const float*)d_in[2];
    const float* emb    = (const float*)d_in[3];
    const float* attn_W = (const float*)d_in[4];
    const float* attn_b = (const float*)d_in[5];
    const float* comb_W = (const float*)d_in[6];
    const float* comb_b = (const float*)d_in[7];
    const float* W_ih   = (const float*)d_in[8];
    const float* W_hh   = (const float*)d_in[9];
    const float* b_ih   = (const float*)d_in[10];
    const float* b_hh   = (const float*)d_in[11];
    const float* out_W  = (const float*)d_in[12];
    const float* out_b  = (const float*)d_in[13];
    float* out = (float*)d_out;

    int dev = 0, nsm = 148;
    cudaGetDevice(&dev);
    cudaDeviceGetAttribute(&nsm, cudaDevAttrMultiProcessorCount, dev);

    const int smem_bytes = RSTAGE * HH * sizeof(float);   // 192 KB dynamic
    cudaFuncSetAttribute(fused_decoder,
                         cudaFuncAttributeMaxDynamicSharedMemorySize, smem_bytes);

    fused_decoder<<<nsm, 1024, smem_bytes>>>(ids, hidden, enc, emb, attn_W, attn_b,
                                             comb_W, comb_b, W_ih, W_hh, b_ih, b_hh,
                                             out_W, out_b, out);
}